// round 1
// baseline (speedup 1.0000x reference)
#include <cuda_runtime.h>
#include <cuda_bf16.h>
#include <math.h>

#define BB 32
#define CC 256
#define OO 256
#define HH 56
#define WW 56
#define CHK 4
#define HWSZ (HH*WW)          // 3136
#define CB 2                  // c-channels per smem stage

// ---- scratch (module-load allocated; allowed) ----
__device__ float g_pooled[BB*CC];                 // [B][C]
__device__ float g_kern[BB*CC*CHK];               // [B][C][4]
__device__ float g_dynw[(size_t)BB*CC*OO*9];      // [B][C][O][9]  ~75.5MB

// ---------------------------------------------------------------
// Kernel 1: global average pool. one block per (b,c)
// ---------------------------------------------------------------
__global__ void pool_kernel(const float* __restrict__ x) {
    __shared__ float red[256];
    int bc = blockIdx.x;                  // 0 .. B*C-1
    const float* p = x + (size_t)bc * HWSZ;
    float s = 0.f;
    for (int i = threadIdx.x; i < HWSZ; i += 256) s += p[i];
    red[threadIdx.x] = s;
    __syncthreads();
    for (int off = 128; off > 0; off >>= 1) {
        if (threadIdx.x < off) red[threadIdx.x] += red[threadIdx.x + off];
        __syncthreads();
    }
    if (threadIdx.x == 0) g_pooled[bc] = red[0] * (1.0f / (float)HWSZ);
}

// ---------------------------------------------------------------
// Kernel 2: h = relu(pooled @ fc1^T); kern = h @ fc2^T + b. one block per b
// ---------------------------------------------------------------
__global__ void fc_kernel(const float* __restrict__ fc1,
                          const float* __restrict__ fc2,
                          const float* __restrict__ fc2b) {
    __shared__ float ps[CC];
    __shared__ float hs[CC];
    int b = blockIdx.x, tid = threadIdx.x;
    ps[tid] = g_pooled[b*CC + tid];
    __syncthreads();
    {
        const float* r1 = fc1 + (size_t)tid * CC;   // fc1_w[tid][j]
        float a = 0.f;
        #pragma unroll 8
        for (int j = 0; j < CC; j++) a = fmaf(ps[j], r1[j], a);
        hs[tid] = fmaxf(a, 0.f);
    }
    __syncthreads();
    #pragma unroll
    for (int m4 = 0; m4 < 4; m4++) {
        int m = m4*CC + tid;                        // 0..1023
        const float* r2 = fc2 + (size_t)m * CC;     // fc2_w[m][j]
        float s = fc2b[m];
        #pragma unroll 8
        for (int j = 0; j < CC; j++) s = fmaf(hs[j], r2[j], s);
        g_kern[b*CC*CHK + m] = s;                   // m = c*4 + t  -> [b][c][t]
    }
}

// ---------------------------------------------------------------
// Kernel 3: dyn_w[b][c][o][k9] = sigmoid(sum_t kern[b,c,t]*cog[o,t,k9]) * weight[o,c,k9]
// linear idx order == output layout (coalesced writes)
// ---------------------------------------------------------------
__global__ void dynw_kernel(const float* __restrict__ cog,
                            const float* __restrict__ weight) {
    size_t idx = (size_t)blockIdx.x * 256 + threadIdx.x;
    const size_t total = (size_t)BB*CC*OO*9;
    if (idx >= total) return;
    int k9 = (int)(idx % 9);
    size_t r = idx / 9;
    int o = (int)(r % OO); r /= OO;
    int c = (int)(r % CC);
    int b = (int)(r / CC);

    const float4 kv = *(const float4*)(g_kern + ((size_t)b*CC + c)*4);
    const float* cg = cog + (size_t)o*36 + k9;      // cog[(o*4+t)*9 + k9]
    float s = kv.x*cg[0] + kv.y*cg[9] + kv.z*cg[18] + kv.w*cg[27];
    float wv = weight[((size_t)o*CC + c)*9 + k9];
    float sig = 1.0f / (1.0f + __expf(-s));
    g_dynw[idx] = sig * wv;
}

// ---------------------------------------------------------------
// Kernel 4: per-sample conv.
// Block: b = blockIdx.z, og = blockIdx.y (0..1 -> 128 o), tile = blockIdx.x (7x7 of 8x8)
// 256 threads: warp id = spatial slot (8 slots of 2x4 pixels), lane = o-lane (32).
// Each thread: 4 o (stride 32) x 2x4 pixels.
// ---------------------------------------------------------------
__global__ __launch_bounds__(256, 2)
void conv_kernel(const float* __restrict__ x, float* __restrict__ out) {
    __shared__ float xs[CB][10][10];
    __shared__ float ws[CB][128*9];

    const int tid  = threadIdx.x;
    const int otid = tid & 31;
    const int stid = tid >> 5;                  // 0..7
    const int th = blockIdx.x / 7, tw = blockIdx.x % 7;
    const int og = blockIdx.y;
    const int b  = blockIdx.z;
    const int sh = (stid >> 1) * 2;             // 0,2,4,6
    const int sw = (stid & 1) * 4;              // 0,4
    const int h0 = th * 8, w0 = tw * 8;

    float acc[4][2][4];
    #pragma unroll
    for (int a = 0; a < 4; a++)
        #pragma unroll
        for (int dy = 0; dy < 2; dy++)
            #pragma unroll
            for (int dx = 0; dx < 4; dx++) acc[a][dy][dx] = 0.f;

    const float* xb = x + (size_t)b * CC * HWSZ;
    const float* wb = g_dynw + (size_t)b * CC * (OO*9) + og * 1152;  // + c*2304 + o_local*9 + k9

    // x-load decode (constant per thread)
    const int xl_cb = tid / 100;
    const int xl_e  = tid % 100;
    const int xl_r  = xl_e / 10;
    const int xl_c  = xl_e % 10;
    const int gh = h0 - 1 + xl_r;
    const int gw = w0 - 1 + xl_c;
    const bool xl_ok = (tid < CB*100) && (gh >= 0) && (gh < HH) && (gw >= 0) && (gw < WW);

    for (int c0 = 0; c0 < CC; c0 += CB) {
        __syncthreads();
        // ---- load x halo tiles (CB * 10*10) ----
        if (tid < CB*100) {
            float v = 0.f;
            if (xl_ok) v = xb[((size_t)(c0 + xl_cb) * HH + gh) * WW + gw];
            xs[xl_cb][xl_r][xl_c] = v;
        }
        // ---- load weights (CB * 1152 contiguous floats per c) ----
        #pragma unroll
        for (int k = 0; k < 9; k++) {
            int e  = k * 256 + tid;            // 0..2303
            int cb = e / 1152;
            int rr = e - cb * 1152;
            ws[cb][rr] = wb[(size_t)(c0 + cb) * 2304 + rr];
        }
        __syncthreads();

        #pragma unroll
        for (int cb = 0; cb < CB; cb++) {
            float xr[4][6];
            #pragma unroll
            for (int r = 0; r < 4; r++)
                #pragma unroll
                for (int cc2 = 0; cc2 < 6; cc2++)
                    xr[r][cc2] = xs[cb][sh + r][sw + cc2];

            #pragma unroll
            for (int o4 = 0; o4 < 4; o4++) {
                const float* wp = &ws[cb][(otid + o4 * 32) * 9];
                #pragma unroll
                for (int i = 0; i < 3; i++) {
                    #pragma unroll
                    for (int j = 0; j < 3; j++) {
                        float wv = wp[i * 3 + j];
                        #pragma unroll
                        for (int dy = 0; dy < 2; dy++)
                            #pragma unroll
                            for (int dx = 0; dx < 4; dx++)
                                acc[o4][dy][dx] = fmaf(wv, xr[dy + i][dx + j], acc[o4][dy][dx]);
                    }
                }
            }
        }
    }

    // ---- store (float4 per row of the 2x4 pixel block) ----
    #pragma unroll
    for (int o4 = 0; o4 < 4; o4++) {
        int o = og * 128 + otid + o4 * 32;
        #pragma unroll
        for (int dy = 0; dy < 2; dy++) {
            int hh = h0 + sh + dy;
            int wcol = w0 + sw;
            float4 v = make_float4(acc[o4][dy][0], acc[o4][dy][1],
                                   acc[o4][dy][2], acc[o4][dy][3]);
            *(float4*)(out + (((size_t)b * OO + o) * HH + hh) * WW + wcol) = v;
        }
    }
}

// ---------------------------------------------------------------
extern "C" void kernel_launch(void* const* d_in, const int* in_sizes, int n_in,
                              void* d_out, int out_size) {
    const float* x      = (const float*)d_in[0];
    const float* fc1_w  = (const float*)d_in[1];
    const float* fc2_w  = (const float*)d_in[2];
    const float* fc2_b  = (const float*)d_in[3];
    const float* cog_w  = (const float*)d_in[4];
    const float* weight = (const float*)d_in[5];
    float* out = (float*)d_out;

    pool_kernel<<<BB*CC, 256>>>(x);
    fc_kernel<<<BB, 256>>>(fc1_w, fc2_w, fc2_b);
    {
        size_t total = (size_t)BB*CC*OO*9;
        int blocks = (int)((total + 255) / 256);
        dynw_kernel<<<blocks, 256>>>(cog_w, weight);
    }
    {
        dim3 grid(49, 2, BB);
        conv_kernel<<<grid, 256>>>(x, out);
    }
}

// round 2
// speedup vs baseline: 1.3481x; 1.3481x over previous
#include <cuda_runtime.h>
#include <cuda_bf16.h>
#include <math.h>

#define BB 32
#define CC 256
#define OO 256
#define HH 56
#define WW 56
#define CHK 4
#define HWSZ (HH*WW)          // 3136
#define CB 4                  // c-channels per pipeline stage
#define NSTG (CC/CB)          // 64 stages
#define WPAD 10               // padded floats per 3x3 filter in g_dynw / smem

// ---- scratch (module-load allocated; allowed) ----
__device__ float g_pooled[BB*CC];                       // [B][C]
__device__ float g_kern[BB*CC*CHK];                     // [B][C][4]
__device__ float g_dynw[(size_t)BB*CC*OO*WPAD];         // [B][C][O][10] ~83.9MB

__device__ __forceinline__ unsigned smem_u32(const void* p) {
    return (unsigned)__cvta_generic_to_shared(p);
}
__device__ __forceinline__ void cp_async16(unsigned dst, const void* src) {
    asm volatile("cp.async.cg.shared.global [%0], [%1], 16;" :: "r"(dst), "l"(src));
}
__device__ __forceinline__ void cp_async4_z(unsigned dst, const void* src, int src_sz) {
    asm volatile("cp.async.ca.shared.global [%0], [%1], 4, %2;" :: "r"(dst), "l"(src), "r"(src_sz));
}

// ---------------------------------------------------------------
// Kernel 1: global average pool. one block per (b,c)
// ---------------------------------------------------------------
__global__ void pool_kernel(const float* __restrict__ x) {
    __shared__ float red[256];
    int bc = blockIdx.x;
    const float* p = x + (size_t)bc * HWSZ;
    float s = 0.f;
    for (int i = threadIdx.x; i < HWSZ; i += 256) s += p[i];
    red[threadIdx.x] = s;
    __syncthreads();
    for (int off = 128; off > 0; off >>= 1) {
        if (threadIdx.x < off) red[threadIdx.x] += red[threadIdx.x + off];
        __syncthreads();
    }
    if (threadIdx.x == 0) g_pooled[bc] = red[0] * (1.0f / (float)HWSZ);
}

// ---------------------------------------------------------------
// Kernel 2: h = relu(pooled @ fc1^T); kern = h @ fc2^T + b. one block per b
// ---------------------------------------------------------------
__global__ void fc_kernel(const float* __restrict__ fc1,
                          const float* __restrict__ fc2,
                          const float* __restrict__ fc2b) {
    __shared__ float ps[CC];
    __shared__ float hs[CC];
    int b = blockIdx.x, tid = threadIdx.x;
    ps[tid] = g_pooled[b*CC + tid];
    __syncthreads();
    {
        const float* r1 = fc1 + (size_t)tid * CC;
        float a = 0.f;
        #pragma unroll 8
        for (int j = 0; j < CC; j++) a = fmaf(ps[j], r1[j], a);
        hs[tid] = fmaxf(a, 0.f);
    }
    __syncthreads();
    #pragma unroll
    for (int m4 = 0; m4 < 4; m4++) {
        int m = m4*CC + tid;                        // 0..1023 = c*4 + t
        const float* r2 = fc2 + (size_t)m * CC;
        float s = fc2b[m];
        #pragma unroll 8
        for (int j = 0; j < CC; j++) s = fmaf(hs[j], r2[j], s);
        g_kern[b*CC*CHK + m] = s;
    }
}

// ---------------------------------------------------------------
// Kernel 3: dyn_w[b][c][o][k] = sigmoid(sum_t kern[b,c,t]*cog[o,t,k]) * weight[o,c,k]
// padded to WPAD=10 floats per filter (k==9 -> 0) for aligned smem loads later.
// ---------------------------------------------------------------
__global__ void dynw_kernel(const float* __restrict__ cog,
                            const float* __restrict__ weight) {
    size_t idx = (size_t)blockIdx.x * 256 + threadIdx.x;
    const size_t total = (size_t)BB*CC*OO*WPAD;
    if (idx >= total) return;
    int k10 = (int)(idx % WPAD);
    size_t r = idx / WPAD;
    int o = (int)(r % OO); r /= OO;
    int c = (int)(r % CC);
    int b = (int)(r / CC);

    float outv = 0.f;
    if (k10 < 9) {
        const float4 kv = *(const float4*)(g_kern + ((size_t)b*CC + c)*4);
        const float* cg = cog + (size_t)o*36 + k10;
        float s = kv.x*cg[0] + kv.y*cg[9] + kv.z*cg[18] + kv.w*cg[27];
        float wv = weight[((size_t)o*CC + c)*9 + k10];
        outv = wv / (1.0f + __expf(-s));
    }
    g_dynw[idx] = outv;
}

// ---------------------------------------------------------------
// Kernel 4: per-sample conv, cp.async double-buffered.
// Block: b = blockIdx.z, og = blockIdx.y (128 o), tile = blockIdx.x (7x7 of 8x8 px)
// 256 threads: warp = spatial slot (2x4 px), lane = o-lane; thread: 4 o x 2x4 px.
// ---------------------------------------------------------------
__global__ __launch_bounds__(256, 2)
void conv_kernel(const float* __restrict__ x, float* __restrict__ out) {
    __shared__ __align__(16) float ws[2][CB][128*WPAD];   // 40960 B
    __shared__ __align__(16) float xs[2][CB][10][12];     //  3840 B

    const int tid  = threadIdx.x;
    const int otid = tid & 31;
    const int stid = tid >> 5;
    const int th = blockIdx.x / 7, tw = blockIdx.x % 7;
    const int og = blockIdx.y;
    const int b  = blockIdx.z;
    const int sh = (stid >> 1) * 2;
    const int sw = (stid & 1) * 4;
    const int h0 = th * 8, w0 = tw * 8;

    float acc[4][2][4];
    #pragma unroll
    for (int a = 0; a < 4; a++)
        #pragma unroll
        for (int dy = 0; dy < 2; dy++)
            #pragma unroll
            for (int dx = 0; dx < 4; dx++) acc[a][dy][dx] = 0.f;

    const float* xb = x + (size_t)b * CC * HWSZ;
    const float* wb = g_dynw + ((size_t)b * CC * OO + (size_t)og * 128) * WPAD;
    // per-c weight slab for this block: 128*WPAD = 1280 contiguous floats at wb + c*OO*WPAD

    // --- x-load decode (2 elements per thread, e = tid, tid+256 < 400) ---
    // element e: cb=e/100, r=(e%100)/10, col=e%10
    int xe0 = tid, xe1 = tid + 256;

    // ---- stage load helper (lambda-free, macro-ish via inline) ----
    #define ISSUE_STAGE(S, BUF)                                                        \
    {                                                                                  \
        const int c0_ = (S) * CB;                                                      \
        _Pragma("unroll")                                                              \
        for (int i = 0; i < 5; i++) {                                                  \
            int chunk = tid + i * 256;            /* 0..1279 */                        \
            int cb_ = chunk / 320;                                                     \
            int cc_ = chunk - cb_ * 320;          /* 16B chunk within c */             \
            const float* src = wb + (size_t)(c0_ + cb_) * (OO*WPAD) + cc_ * 4;         \
            cp_async16(smem_u32(&ws[BUF][cb_][cc_ * 4]), src);                         \
        }                                                                              \
        _Pragma("unroll")                                                              \
        for (int q = 0; q < 2; q++) {                                                  \
            int e = q ? xe1 : xe0;                                                     \
            if (e < CB * 100) {                                                        \
                int cb_ = e / 100;                                                     \
                int rr_ = (e - cb_ * 100) / 10;                                        \
                int c2_ = e % 10;                                                      \
                int gh_ = h0 - 1 + rr_;                                                \
                int gw_ = w0 - 1 + c2_;                                                \
                bool ok = (gh_ >= 0) && (gh_ < HH) && (gw_ >= 0) && (gw_ < WW);        \
                const float* src = ok ? (xb + ((size_t)(c0_ + cb_) * HH + gh_) * WW + gw_) : xb; \
                cp_async4_z(smem_u32(&xs[BUF][cb_][rr_][c2_]), src, ok ? 4 : 0);       \
            }                                                                          \
        }                                                                              \
    }

    // prologue: stage 0 into buf 0
    ISSUE_STAGE(0, 0);
    asm volatile("cp.async.commit_group;");

    for (int s = 0; s < NSTG; s++) {
        const int cur = s & 1;
        if (s + 1 < NSTG) ISSUE_STAGE(s + 1, cur ^ 1);
        asm volatile("cp.async.commit_group;");
        asm volatile("cp.async.wait_group 1;");
        __syncthreads();

        #pragma unroll
        for (int cb = 0; cb < CB; cb++) {
            float xr[4][6];
            #pragma unroll
            for (int r = 0; r < 4; r++) {
                float4 v4 = *(const float4*)&xs[cur][cb][sh + r][sw];
                float2 v2 = *(const float2*)&xs[cur][cb][sh + r][sw + 4];
                xr[r][0] = v4.x; xr[r][1] = v4.y; xr[r][2] = v4.z; xr[r][3] = v4.w;
                xr[r][4] = v2.x; xr[r][5] = v2.y;
            }
            #pragma unroll
            for (int o4 = 0; o4 < 4; o4++) {
                const float* wp = &ws[cur][cb][(otid + o4 * 32) * WPAD];
                float2 a0 = *(const float2*)(wp + 0);
                float2 a1 = *(const float2*)(wp + 2);
                float2 a2 = *(const float2*)(wp + 4);
                float2 a3 = *(const float2*)(wp + 6);
                float w8  = wp[8];
                float wv[9] = {a0.x, a0.y, a1.x, a1.y, a2.x, a2.y, a3.x, a3.y, w8};
                #pragma unroll
                for (int i = 0; i < 3; i++) {
                    #pragma unroll
                    for (int j = 0; j < 3; j++) {
                        float wcur = wv[i * 3 + j];
                        #pragma unroll
                        for (int dy = 0; dy < 2; dy++)
                            #pragma unroll
                            for (int dx = 0; dx < 4; dx++)
                                acc[o4][dy][dx] = fmaf(wcur, xr[dy + i][dx + j], acc[o4][dy][dx]);
                    }
                }
            }
        }
        __syncthreads();
    }
    #undef ISSUE_STAGE

    // ---- store ----
    #pragma unroll
    for (int o4 = 0; o4 < 4; o4++) {
        int o = og * 128 + otid + o4 * 32;
        #pragma unroll
        for (int dy = 0; dy < 2; dy++) {
            int hh = h0 + sh + dy;
            int wcol = w0 + sw;
            float4 v = make_float4(acc[o4][dy][0], acc[o4][dy][1],
                                   acc[o4][dy][2], acc[o4][dy][3]);
            *(float4*)(out + (((size_t)b * OO + o) * HH + hh) * WW + wcol) = v;
        }
    }
}

// ---------------------------------------------------------------
extern "C" void kernel_launch(void* const* d_in, const int* in_sizes, int n_in,
                              void* d_out, int out_size) {
    const float* x      = (const float*)d_in[0];
    const float* fc1_w  = (const float*)d_in[1];
    const float* fc2_w  = (const float*)d_in[2];
    const float* fc2_b  = (const float*)d_in[3];
    const float* cog_w  = (const float*)d_in[4];
    const float* weight = (const float*)d_in[5];
    float* out = (float*)d_out;

    pool_kernel<<<BB*CC, 256>>>(x);
    fc_kernel<<<BB, 256>>>(fc1_w, fc2_w, fc2_b);
    {
        size_t total = (size_t)BB*CC*OO*WPAD;
        int blocks = (int)((total + 255) / 256);
        dynw_kernel<<<blocks, 256>>>(cog_w, weight);
    }
    {
        dim3 grid(49, 2, BB);
        conv_kernel<<<grid, 256>>>(x, out);
    }
}